// round 12
// baseline (speedup 1.0000x reference)
#include <cuda_runtime.h>
#include <cuda_bf16.h>
#include <stdint.h>

// ---------------- problem constants ----------------
#define NB 4096
#define HB 128
#define TD 768
#define TILES 32
#define KCH 64                           // bf16 K per smem chunk (128B rows, SW128)
#define INV_TEMP 5.0f
#define HASH_SCALE 0.08838834764831845f  // 1/sqrt(128)
#define TRI_BLOCKS (TILES * (TILES + 1) / 2)  // 528 (both cont and distill use triangle)

// ---------------- device scratch ----------------
__device__ __nv_bfloat16 g_LNh[NB * HB];  // normalized logits (bf16)
__device__ __nv_bfloat16 g_Hs[NB * HB];   // hash * 1/sqrt(128) (bf16)
__device__ __nv_bfloat16 g_TNh[NB * TD];  // normalized teacher
__device__ __nv_bfloat16 g_TNn[NB * TD];  // negated normalized teacher
__device__ float g_denom[NB], g_pos[NB], g_cnt[NB];
__device__ float g_distill;               // distill SSE (zeroed in prep)
__device__ float g_qpart[NB / 8];         // per-block quant partials (plain stores)

// ---------------- helpers ----------------
__device__ __forceinline__ uint32_t smem_u32(const void* p) {
  uint32_t a;
  asm("{ .reg .u64 t; cvta.to.shared.u64 t, %1; cvt.u32.u64 %0, t; }" : "=r"(a) : "l"(p));
  return a;
}

__device__ __forceinline__ void ldsm4(uint32_t* r, uint32_t addr) {
  asm volatile("ldmatrix.sync.aligned.m8n8.x4.shared.b16 {%0,%1,%2,%3}, [%4];"
               : "=r"(r[0]), "=r"(r[1]), "=r"(r[2]), "=r"(r[3]) : "r"(addr));
}

__device__ __forceinline__ void mma16816(float* c, const uint32_t* a, const uint32_t* b) {
  asm volatile(
      "mma.sync.aligned.m16n8k16.row.col.f32.bf16.bf16.f32 "
      "{%0,%1,%2,%3}, {%4,%5,%6,%7}, {%8,%9}, {%0,%1,%2,%3};"
      : "+f"(c[0]), "+f"(c[1]), "+f"(c[2]), "+f"(c[3])
      : "r"(a[0]), "r"(a[1]), "r"(a[2]), "r"(a[3]), "r"(b[0]), "r"(b[1]));
}

// ---------------- fused prep: zero accs + normalize logits/teacher + scale hash ----------------
__global__ void __launch_bounds__(256) prep_kernel(const float* __restrict__ logits,
                                                   const float* __restrict__ hash,
                                                   const float* __restrict__ teacher) {
  const int tid = threadIdx.x;
  {
    const int idx = blockIdx.x * 256 + tid;
    if (idx < NB) { g_denom[idx] = 0.f; g_pos[idx] = 0.f; g_cnt[idx] = 0.f; }
    if (idx == 0) g_distill = 0.f;
  }
  const int row = blockIdx.x * 8 + (tid >> 5);
  const int lane = tid & 31;

  // ---- logits: normalize + quant partial ----
  const float4 v = *reinterpret_cast<const float4*>(logits + (size_t)row * HB + lane * 4);
  float ss = v.x * v.x + v.y * v.y + v.z * v.z + v.w * v.w;
  float q = fabsf(fabsf(v.x) - 1.f) + fabsf(fabsf(v.y) - 1.f) +
            fabsf(fabsf(v.z) - 1.f) + fabsf(fabsf(v.w) - 1.f);
#pragma unroll
  for (int o = 16; o > 0; o >>= 1) {
    ss += __shfl_xor_sync(0xffffffffu, ss, o);
    q += __shfl_xor_sync(0xffffffffu, q, o);
  }
  const float sc = 1.0f / fmaxf(sqrtf(ss), 1e-12f);
  __nv_bfloat162* lo = reinterpret_cast<__nv_bfloat162*>(g_LNh + (size_t)row * HB + lane * 4);
  lo[0] = __floats2bfloat162_rn(v.x * sc, v.y * sc);
  lo[1] = __floats2bfloat162_rn(v.z * sc, v.w * sc);

  __shared__ float s_q[8];
  if (lane == 0) s_q[tid >> 5] = q;
  __syncthreads();
  if (tid == 0) {
    float t = 0.f;
#pragma unroll
    for (int w = 0; w < 8; w++) t += s_q[w];
    g_qpart[blockIdx.x] = t;
  }

  // ---- hash: scale by 1/sqrt(128) ----
  const float4 h = *reinterpret_cast<const float4*>(hash + (size_t)row * HB + lane * 4);
  __nv_bfloat162* ho = reinterpret_cast<__nv_bfloat162*>(g_Hs + (size_t)row * HB + lane * 4);
  ho[0] = __floats2bfloat162_rn(h.x * HASH_SCALE, h.y * HASH_SCALE);
  ho[1] = __floats2bfloat162_rn(h.z * HASH_SCALE, h.w * HASH_SCALE);

  // ---- teacher: normalize (+ and -) ----
  float4 tv[6];
  float ts = 0.f;
#pragma unroll
  for (int s = 0; s < 6; s++) {
    tv[s] = *reinterpret_cast<const float4*>(teacher + (size_t)row * TD + s * 128 + lane * 4);
    ts += tv[s].x * tv[s].x + tv[s].y * tv[s].y + tv[s].z * tv[s].z + tv[s].w * tv[s].w;
  }
#pragma unroll
  for (int o = 16; o > 0; o >>= 1) ts += __shfl_xor_sync(0xffffffffu, ts, o);
  const float tsc = 1.0f / fmaxf(sqrtf(ts), 1e-12f);
#pragma unroll
  for (int s = 0; s < 6; s++) {
    const size_t idx = (size_t)row * TD + s * 128 + lane * 4;
    __nv_bfloat162* tp = reinterpret_cast<__nv_bfloat162*>(g_TNh + idx);
    __nv_bfloat162* tn = reinterpret_cast<__nv_bfloat162*>(g_TNn + idx);
    tp[0] = __floats2bfloat162_rn(tv[s].x * tsc, tv[s].y * tsc);
    tp[1] = __floats2bfloat162_rn(tv[s].z * tsc, tv[s].w * tsc);
    tn[0] = __floats2bfloat162_rn(-tv[s].x * tsc, -tv[s].y * tsc);
    tn[1] = __floats2bfloat162_rn(-tv[s].z * tsc, -tv[s].w * tsc);
  }
}

// ---------------- chunk source selection ----------------
template <bool DISTILL>
__device__ __forceinline__ void chunk_src(int c, const __nv_bfloat16*& A,
                                          const __nv_bfloat16*& B, int& ld, int& kb) {
  if (!DISTILL) { A = g_LNh; B = g_LNh; ld = HB; kb = c * KCH; }
  else if (c < 2) { A = g_Hs; B = g_Hs; ld = HB; kb = c * KCH; }
  else { A = g_TNh; B = g_TNn; ld = TD; kb = (c - 2) * KCH; }
}

// ---------------- stage one 128x64(bf16) A/B chunk pair via cp.async ----------------
__device__ __forceinline__ void cp_chunk(uint32_t sA, uint32_t sB,
                                         const __nv_bfloat16* __restrict__ A, int lda,
                                         const __nv_bfloat16* __restrict__ Bp, int ldb,
                                         int rbase, int cbase, int kb, int tid) {
#pragma unroll
  for (int p = 0; p < 4; p++) {
    const int lin = p * 256 + tid;  // 0..1023 x 16B segments
    const int row = lin >> 3, seg = lin & 7;
    const uint32_t off = (uint32_t)(row * 128 + seg * 16);
    const uint32_t swz = off ^ ((off >> 3) & 0x70);
    const unsigned long long ga =
        (unsigned long long)__cvta_generic_to_global(A + (size_t)(rbase + row) * lda + kb + seg * 8);
    const unsigned long long gb =
        (unsigned long long)__cvta_generic_to_global(Bp + (size_t)(cbase + row) * ldb + kb + seg * 8);
    asm volatile("cp.async.cg.shared.global [%0], [%1], 16;\n" ::"r"(sA + swz), "l"(ga));
    asm volatile("cp.async.cg.shared.global [%0], [%1], 16;\n" ::"r"(sB + swz), "l"(gb));
  }
  asm volatile("cp.async.commit_group;\n" ::: "memory");
}

// ---------------- double-buffered HMMA mainloop (warp tile 64x32) ----------------
template <bool DISTILL>
__device__ __forceinline__ void mma_mainloop(float acc[4][4][4], int rbase, int cbase,
                                             int tid, uint32_t sbase) {
  const int NC = DISTILL ? (HB + TD) / KCH : HB / KCH;  // 14 or 2
  const int lane = tid & 31, wid = tid >> 5;
  const int wm = (wid >> 2) * 64, wn = (wid & 3) * 32;

  const int arow = wm + (lane & 15);
  const uint32_t aX = (uint32_t)(arow & 7) << 4;
  const uint32_t aSub = (uint32_t)((lane >> 4) * 16);
  const uint32_t aRow = (uint32_t)arow * 128u;
  const int brow = wn + (lane & 7) + ((lane >> 4) & 1) * 8;
  const uint32_t bX = (uint32_t)(brow & 7) << 4;
  const uint32_t bSub = (uint32_t)(((lane >> 3) & 1) * 16);
  const uint32_t bRow = (uint32_t)brow * 128u;

  {  // prefetch chunks 0,1
    const __nv_bfloat16 *A, *B; int ld, kb;
    chunk_src<DISTILL>(0, A, B, ld, kb);
    cp_chunk(sbase, sbase + 16384u, A, ld, B, ld, rbase, cbase, kb, tid);
    chunk_src<DISTILL>(1, A, B, ld, kb);
    cp_chunk(sbase + 32768u, sbase + 49152u, A, ld, B, ld, rbase, cbase, kb, tid);
  }

  for (int c = 0; c < NC; c++) {
    const int b = c & 1;
    const uint32_t sAb = sbase + (uint32_t)b * 32768u;
    const uint32_t sBb = sAb + 16384u;
    if (c == NC - 1) asm volatile("cp.async.wait_group 0;\n" ::: "memory");
    else             asm volatile("cp.async.wait_group 1;\n" ::: "memory");
    __syncthreads();

    const uint32_t aRB = sAb + aRow;
    const uint32_t bRB = sBb + bRow;
#pragma unroll
    for (int ks = 0; ks < 4; ks++) {
      const uint32_t acol = ((uint32_t)(ks * 32) + aSub) ^ aX;
      const uint32_t bcol = ((uint32_t)(ks * 32) + bSub) ^ bX;
      uint32_t af[4][4], bf0[4], bf1[4];
#pragma unroll
      for (int mt = 0; mt < 4; mt++) ldsm4(af[mt], aRB + mt * 2048u + acol);
      ldsm4(bf0, bRB + bcol);
      ldsm4(bf1, bRB + 2048u + bcol);
#pragma unroll
      for (int mt = 0; mt < 4; mt++) {
        mma16816(acc[mt][0], af[mt], &bf0[0]);
        mma16816(acc[mt][1], af[mt], &bf0[2]);
        mma16816(acc[mt][2], af[mt], &bf1[0]);
        mma16816(acc[mt][3], af[mt], &bf1[2]);
      }
    }
    __syncthreads();
    if (c + 2 < NC) {
      const __nv_bfloat16 *A, *B; int ld, kb;
      chunk_src<DISTILL>(c + 2, A, B, ld, kb);
      cp_chunk(sAb, sBb, A, ld, B, ld, rbase, cbase, kb, tid);
    }
  }
}

// ---------------- mask tile staging (dtype-robust) ----------------
__device__ __forceinline__ void stage_mask(uint8_t* mk, const uint8_t* __restrict__ mraw,
                                           int rb, int cb, int tid, bool is_u8) {
  if (is_u8) {
#pragma unroll
    for (int p = 0; p < 4; p++) {
      const int idx = tid + p * 256;
      const int row = idx >> 3, q = idx & 7;
      const uint4 v = *reinterpret_cast<const uint4*>(
          mraw + (size_t)(rb + row) * NB + cb + q * 16);
      *reinterpret_cast<uint4*>(&mk[row * 128 + q * 16]) = v;
    }
  } else {
    const uint32_t* m32 = reinterpret_cast<const uint32_t*>(mraw);
#pragma unroll
    for (int p = 0; p < 16; p++) {
      const int idx = tid + p * 256;
      const int row = idx >> 5, q = idx & 31;
      const uint4 v = *reinterpret_cast<const uint4*>(
          m32 + (size_t)(rb + row) * NB + cb + q * 4);
      uint8_t* d = &mk[row * 128 + q * 4];
      d[0] = (v.x != 0u); d[1] = (v.y != 0u); d[2] = (v.z != 0u); d[3] = (v.w != 0u);
    }
  }
}

// ---------------- i-side (row) epilogue from registers ----------------
template <bool DIAG>
__device__ __forceinline__ void cont_rows(const float acc[4][4][4], const uint8_t* mk,
                                          int rbase, int cbase, int tid) {
  const int lane = tid & 31, wid = tid >> 5;
  const int wm = (wid >> 2) * 64, wn = (wid & 3) * 32;
#pragma unroll
  for (int mt = 0; mt < 4; mt++) {
#pragma unroll
    for (int half = 0; half < 2; half++) {
      const int rl = wm + mt * 16 + (lane >> 2) + half * 8;
      const int gi = rbase + rl;
      float dsum = 0.f, psum = 0.f, csum = 0.f;
#pragma unroll
      for (int nt = 0; nt < 4; nt++) {
#pragma unroll
        for (int e = 0; e < 2; e++) {
          const int cl = wn + nt * 8 + (lane & 3) * 2 + e;
          const float s = acc[mt][nt][half * 2 + e] * INV_TEMP;
          if (!DIAG || gi != cbase + cl) dsum += __expf(s - INV_TEMP);
          if (mk[rl * 128 + cl]) { psum += s; csum += 1.f; }
        }
      }
      dsum += __shfl_down_sync(0xffffffffu, dsum, 2, 4);
      dsum += __shfl_down_sync(0xffffffffu, dsum, 1, 4);
      psum += __shfl_down_sync(0xffffffffu, psum, 2, 4);
      psum += __shfl_down_sync(0xffffffffu, psum, 1, 4);
      csum += __shfl_down_sync(0xffffffffu, csum, 2, 4);
      csum += __shfl_down_sync(0xffffffffu, csum, 1, 4);
      if ((lane & 3) == 0) {
        atomicAdd(&g_denom[gi], dsum);
        atomicAdd(&g_pos[gi], psum);
        atomicAdd(&g_cnt[gi], csum);
      }
    }
  }
}

// ---- fused pair kernel: distill triangle [0,528) + cont triangle [528,1056) ----
__global__ void __launch_bounds__(256, 2) pair_kernel(const uint8_t* __restrict__ mraw) {
  extern __shared__ char dsm[];
  char* dal = (char*)(((uintptr_t)dsm + 1023) & ~(uintptr_t)1023);
  const uint32_t sbase = smem_u32(dal);
  const int tid = threadIdx.x;
  __shared__ uint8_t mk[128 * 128];
  __shared__ uint8_t mk2[128 * 128];

  float acc[4][4][4];
#pragma unroll
  for (int m = 0; m < 4; m++)
#pragma unroll
    for (int n = 0; n < 4; n++)
#pragma unroll
      for (int r = 0; r < 4; r++) acc[m][n][r] = 0.f;

  // triangle decode (shared by both halves)
  const bool is_dist = (blockIdx.x < TRI_BLOCKS);
  int p = is_dist ? blockIdx.x : (blockIdx.x - TRI_BLOCKS);
  int ti = 0;
  while (p >= TILES - ti) { p -= TILES - ti; ti++; }
  const int tj = ti + p;
  const int rbase = ti * 128, cbase = tj * 128;

  if (is_dist) {
    // ================= distillation =================
    const float wgt = (ti == tj) ? 1.f : 2.f;
    mma_mainloop<true>(acc, rbase, cbase, tid, sbase);

    float ss = 0.f;
#pragma unroll
    for (int m = 0; m < 4; m++)
#pragma unroll
      for (int n = 0; n < 4; n++)
#pragma unroll
        for (int r = 0; r < 4; r++) ss = fmaf(acc[m][n][r], acc[m][n][r], ss);
#pragma unroll
    for (int o = 16; o > 0; o >>= 1) ss += __shfl_down_sync(0xffffffffu, ss, o);
    __shared__ float red[8];
    if ((tid & 31) == 0) red[tid >> 5] = ss;
    __syncthreads();
    if (tid < 8) {
      float v = red[tid];
#pragma unroll
      for (int o = 4; o > 0; o >>= 1) v += __shfl_down_sync(0x000000ffu, v, o);
      if (tid == 0) atomicAdd(&g_distill, v * wgt);
    }
  } else {
    // ================= contrastive (triangle, two-sided) =================
    mma_mainloop<false>(acc, rbase, cbase, tid, sbase);
    const bool is_u8 = (mraw[4097] != 0);

    if (ti == tj) {
      // diagonal tile: row-side only, with diag skip
      stage_mask(mk, mraw, rbase, cbase, tid, is_u8);
      __syncthreads();
      cont_rows<true>(acc, mk, rbase, cbase, tid);
    } else {
      // off-diagonal: rows for i-block from registers, cols for j-block via smem S
      stage_mask(mk, mraw, rbase, cbase, tid, is_u8);   // mask[i-block][j-block]
      stage_mask(mk2, mraw, cbase, rbase, tid, is_u8);  // mask[j-block][i-block]

      // spill s = 5*sim into padded smem tile S[128][132]
      float* S = (float*)dal;
      const int lane = tid & 31, wid = tid >> 5;
      const int wm = (wid >> 2) * 64, wn = (wid & 3) * 32;
#pragma unroll
      for (int mt = 0; mt < 4; mt++) {
#pragma unroll
        for (int half = 0; half < 2; half++) {
          const int rl = wm + mt * 16 + (lane >> 2) + half * 8;
#pragma unroll
          for (int nt = 0; nt < 4; nt++) {
            const int cl = wn + nt * 8 + (lane & 3) * 2;
            float2 sv;
            sv.x = acc[mt][nt][half * 2 + 0] * INV_TEMP;
            sv.y = acc[mt][nt][half * 2 + 1] * INV_TEMP;
            *reinterpret_cast<float2*>(&S[rl * 132 + cl]) = sv;
          }
        }
      }
      __syncthreads();

      // i-side: row sums for rows rbase.. (no diag elements in off-diag tiles)
      cont_rows<false>(acc, mk, rbase, cbase, tid);

      // j-side: column sums -> rows cbase+c (sim symmetric: sim[j][i] = S[i][j])
      {
        const int c = tid >> 1, par = tid & 1;
        const uint8_t* m2 = &mk2[c * 128];
        float dsum = 0.f, psum = 0.f, csum = 0.f;
#pragma unroll 8
        for (int k = 0; k < 64; k++) {
          const int r = k * 2 + par;  // parity-interleaved rows: bank-friendly
          const float s = S[r * 132 + c];
          dsum += __expf(s - INV_TEMP);
          if (m2[r]) { psum += s; csum += 1.f; }
        }
        dsum += __shfl_down_sync(0xffffffffu, dsum, 1, 2);
        psum += __shfl_down_sync(0xffffffffu, psum, 1, 2);
        csum += __shfl_down_sync(0xffffffffu, csum, 1, 2);
        if (par == 0) {
          atomicAdd(&g_denom[cbase + c], dsum);
          atomicAdd(&g_pos[cbase + c], psum);
          atomicAdd(&g_cnt[cbase + c], csum);
        }
      }
    }
  }
}

// ---------------- finalize ----------------
__global__ void finalize_kernel(float* __restrict__ out) {
  __shared__ double red[256];
  __shared__ float redq[256];
  double s = 0.0;
  for (int r = threadIdx.x; r < NB; r += 256) {
    const float c = fmaxf(g_cnt[r], 1.f);
    s += (double)(INV_TEMP + logf(g_denom[r]) - g_pos[r] / c);
  }
  float q = 0.f;
  for (int r = threadIdx.x; r < NB / 8; r += 256) q += g_qpart[r];
  red[threadIdx.x] = s;
  redq[threadIdx.x] = q;
  __syncthreads();
  for (int o = 128; o > 0; o >>= 1) {
    if (threadIdx.x < o) {
      red[threadIdx.x] += red[threadIdx.x + o];
      redq[threadIdx.x] += redq[threadIdx.x + o];
    }
    __syncthreads();
  }
  if (threadIdx.x == 0) {
    const double cont = red[0] / (double)NB;
    const double dist = (double)g_distill / ((double)NB * (double)NB);
    const double quant = (double)redq[0] / ((double)NB * (double)HB);
    out[0] = (float)(cont + 0.5 * dist + 0.01 * quant);
  }
}

// ---------------- launch ----------------
extern "C" void kernel_launch(void* const* d_in, const int* in_sizes, int n_in,
                              void* d_out, int out_size) {
  const float* logits = (const float*)d_in[0];
  const float* hash = (const float*)d_in[1];
  const float* teacher = (const float*)d_in[2];
  const uint8_t* mask = (const uint8_t*)d_in[3];
  float* out = (float*)d_out;
  (void)in_sizes; (void)n_in; (void)out_size;

  // dynamic smem: max(GEMM double-buffer 64KB, S tile 128*132*4 = 67.6KB) + align slack
  const int DSM = 128 * 132 * 4 + 1024;
  cudaFuncSetAttribute(pair_kernel, cudaFuncAttributeMaxDynamicSharedMemorySize, DSM);

  prep_kernel<<<NB / 8, 256>>>(logits, hash, teacher);
  pair_kernel<<<2 * TRI_BLOCKS, 256, DSM>>>(mask);
  finalize_kernel<<<1, 256>>>(out);
}

// round 13
// speedup vs baseline: 1.1133x; 1.1133x over previous
#include <cuda_runtime.h>
#include <cuda_bf16.h>
#include <stdint.h>

// ---------------- problem constants ----------------
#define NB 4096
#define HB 128
#define TD 768
#define TILES 32
#define KCH 64                           // bf16 K per smem chunk (128B rows, SW128)
#define INV_TEMP 5.0f
#define HASH_SCALE 0.08838834764831845f  // 1/sqrt(128)
#define CONT_BLOCKS (TILES * TILES)                  // 1024
#define DIST_BLOCKS (TILES * (TILES + 1) / 2)        // 528 (launched FIRST: heavy blocks early)
#define BUF_BYTES 32768u                              // one A+B chunk pair (16K + 16K)

// ---------------- device scratch ----------------
__device__ __nv_bfloat16 g_LNh[NB * HB];  // normalized logits (bf16)
__device__ __nv_bfloat16 g_Hs[NB * HB];   // hash * 1/sqrt(128) (bf16)
__device__ __nv_bfloat16 g_TNh[NB * TD];  // normalized teacher
__device__ __nv_bfloat16 g_TNn[NB * TD];  // negated normalized teacher
__device__ float g_denom[NB], g_pos[NB], g_cnt[NB];
__device__ float g_distill;               // distill SSE (zeroed in prep)
__device__ float g_qpart[NB / 4];         // per-block quant partials (plain stores)

// ---------------- helpers ----------------
__device__ __forceinline__ uint32_t smem_u32(const void* p) {
  uint32_t a;
  asm("{ .reg .u64 t; cvta.to.shared.u64 t, %1; cvt.u32.u64 %0, t; }" : "=r"(a) : "l"(p));
  return a;
}

__device__ __forceinline__ void ldsm4(uint32_t* r, uint32_t addr) {
  asm volatile("ldmatrix.sync.aligned.m8n8.x4.shared.b16 {%0,%1,%2,%3}, [%4];"
               : "=r"(r[0]), "=r"(r[1]), "=r"(r[2]), "=r"(r[3]) : "r"(addr));
}

__device__ __forceinline__ void mma16816(float* c, const uint32_t* a, const uint32_t* b) {
  asm volatile(
      "mma.sync.aligned.m16n8k16.row.col.f32.bf16.bf16.f32 "
      "{%0,%1,%2,%3}, {%4,%5,%6,%7}, {%8,%9}, {%0,%1,%2,%3};"
      : "+f"(c[0]), "+f"(c[1]), "+f"(c[2]), "+f"(c[3])
      : "r"(a[0]), "r"(a[1]), "r"(a[2]), "r"(a[3]), "r"(b[0]), "r"(b[1]));
}

// ---------------- fused prep: zero accs + normalize logits/teacher + scale hash ----------------
// 1024 blocks x 128 threads; one warp per row (4 rows/block) for latency hiding.
__global__ void __launch_bounds__(128) prep_kernel(const float* __restrict__ logits,
                                                   const float* __restrict__ hash,
                                                   const float* __restrict__ teacher) {
  const int tid = threadIdx.x;
  {
    const int idx = blockIdx.x * 128 + tid;
    if (idx < NB) { g_denom[idx] = 0.f; g_pos[idx] = 0.f; g_cnt[idx] = 0.f; }
    if (idx == 0) g_distill = 0.f;
  }
  const int row = blockIdx.x * 4 + (tid >> 5);
  const int lane = tid & 31;

  // ---- logits: normalize + quant partial ----
  const float4 v = *reinterpret_cast<const float4*>(logits + (size_t)row * HB + lane * 4);
  float ss = v.x * v.x + v.y * v.y + v.z * v.z + v.w * v.w;
  float q = fabsf(fabsf(v.x) - 1.f) + fabsf(fabsf(v.y) - 1.f) +
            fabsf(fabsf(v.z) - 1.f) + fabsf(fabsf(v.w) - 1.f);
#pragma unroll
  for (int o = 16; o > 0; o >>= 1) {
    ss += __shfl_xor_sync(0xffffffffu, ss, o);
    q += __shfl_xor_sync(0xffffffffu, q, o);
  }
  const float sc = 1.0f / fmaxf(sqrtf(ss), 1e-12f);
  __nv_bfloat162* lo = reinterpret_cast<__nv_bfloat162*>(g_LNh + (size_t)row * HB + lane * 4);
  lo[0] = __floats2bfloat162_rn(v.x * sc, v.y * sc);
  lo[1] = __floats2bfloat162_rn(v.z * sc, v.w * sc);

  __shared__ float s_q[4];
  if (lane == 0) s_q[tid >> 5] = q;
  __syncthreads();
  if (tid == 0) g_qpart[blockIdx.x] = s_q[0] + s_q[1] + s_q[2] + s_q[3];

  // ---- hash: scale by 1/sqrt(128) ----
  const float4 h = *reinterpret_cast<const float4*>(hash + (size_t)row * HB + lane * 4);
  __nv_bfloat162* ho = reinterpret_cast<__nv_bfloat162*>(g_Hs + (size_t)row * HB + lane * 4);
  ho[0] = __floats2bfloat162_rn(h.x * HASH_SCALE, h.y * HASH_SCALE);
  ho[1] = __floats2bfloat162_rn(h.z * HASH_SCALE, h.w * HASH_SCALE);

  // ---- teacher: normalize (+ and -) ----
  float4 tv[6];
  float ts = 0.f;
#pragma unroll
  for (int s = 0; s < 6; s++) {
    tv[s] = *reinterpret_cast<const float4*>(teacher + (size_t)row * TD + s * 128 + lane * 4);
    ts += tv[s].x * tv[s].x + tv[s].y * tv[s].y + tv[s].z * tv[s].z + tv[s].w * tv[s].w;
  }
#pragma unroll
  for (int o = 16; o > 0; o >>= 1) ts += __shfl_xor_sync(0xffffffffu, ts, o);
  const float tsc = 1.0f / fmaxf(sqrtf(ts), 1e-12f);
#pragma unroll
  for (int s = 0; s < 6; s++) {
    const size_t idx = (size_t)row * TD + s * 128 + lane * 4;
    __nv_bfloat162* tp = reinterpret_cast<__nv_bfloat162*>(g_TNh + idx);
    __nv_bfloat162* tn = reinterpret_cast<__nv_bfloat162*>(g_TNn + idx);
    tp[0] = __floats2bfloat162_rn(tv[s].x * tsc, tv[s].y * tsc);
    tp[1] = __floats2bfloat162_rn(tv[s].z * tsc, tv[s].w * tsc);
    tn[0] = __floats2bfloat162_rn(-tv[s].x * tsc, -tv[s].y * tsc);
    tn[1] = __floats2bfloat162_rn(-tv[s].z * tsc, -tv[s].w * tsc);
  }
}

// ---------------- chunk source selection ----------------
template <bool DISTILL>
__device__ __forceinline__ void chunk_src(int c, const __nv_bfloat16*& A,
                                          const __nv_bfloat16*& B, int& ld, int& kb) {
  if (!DISTILL) { A = g_LNh; B = g_LNh; ld = HB; kb = c * KCH; }
  else if (c < 2) { A = g_Hs; B = g_Hs; ld = HB; kb = c * KCH; }
  else { A = g_TNh; B = g_TNn; ld = TD; kb = (c - 2) * KCH; }
}

// ---------------- stage one 128x64(bf16) A/B chunk pair via cp.async ----------------
__device__ __forceinline__ void cp_chunk(uint32_t sA, uint32_t sB,
                                         const __nv_bfloat16* __restrict__ A, int lda,
                                         const __nv_bfloat16* __restrict__ Bp, int ldb,
                                         int rbase, int cbase, int kb, int tid) {
#pragma unroll
  for (int p = 0; p < 4; p++) {
    const int lin = p * 256 + tid;  // 0..1023 x 16B segments
    const int row = lin >> 3, seg = lin & 7;
    const uint32_t off = (uint32_t)(row * 128 + seg * 16);
    const uint32_t swz = off ^ ((off >> 3) & 0x70);
    const unsigned long long ga =
        (unsigned long long)__cvta_generic_to_global(A + (size_t)(rbase + row) * lda + kb + seg * 8);
    const unsigned long long gb =
        (unsigned long long)__cvta_generic_to_global(Bp + (size_t)(cbase + row) * ldb + kb + seg * 8);
    asm volatile("cp.async.cg.shared.global [%0], [%1], 16;\n" ::"r"(sA + swz), "l"(ga));
    asm volatile("cp.async.cg.shared.global [%0], [%1], 16;\n" ::"r"(sB + swz), "l"(gb));
  }
  asm volatile("cp.async.commit_group;\n" ::: "memory");
}

// ---------------- 3-stage pipelined HMMA mainloop (warp tile 64x32) ----------------
// Stage buffers at sbase + (c%3)*BUF_BYTES. Prefetch of chunk c+2 is issued BEFORE
// compute of chunk c (its target buffer was last read at chunk c-1; the top-of-loop
// __syncthreads orders that). One sync per chunk.
template <bool DISTILL>
__device__ __forceinline__ void mma_mainloop(float acc[4][4][4], int rbase, int cbase,
                                             int tid, uint32_t sbase) {
  const int NC = DISTILL ? (HB + TD) / KCH : HB / KCH;  // 14 or 2
  const int lane = tid & 31, wid = tid >> 5;
  const int wm = (wid >> 2) * 64, wn = (wid & 3) * 32;

  const int arow = wm + (lane & 15);
  const uint32_t aX = (uint32_t)(arow & 7) << 4;
  const uint32_t aSub = (uint32_t)((lane >> 4) * 16);
  const uint32_t aRow = (uint32_t)arow * 128u;
  const int brow = wn + (lane & 7) + ((lane >> 4) & 1) * 8;
  const uint32_t bX = (uint32_t)(brow & 7) << 4;
  const uint32_t bSub = (uint32_t)(((lane >> 3) & 1) * 16);
  const uint32_t bRow = (uint32_t)brow * 128u;

  {  // prefetch chunks 0,1
    const __nv_bfloat16 *A, *B; int ld, kb;
    chunk_src<DISTILL>(0, A, B, ld, kb);
    cp_chunk(sbase, sbase + 16384u, A, ld, B, ld, rbase, cbase, kb, tid);
    chunk_src<DISTILL>(1, A, B, ld, kb);
    cp_chunk(sbase + BUF_BYTES, sbase + BUF_BYTES + 16384u, A, ld, B, ld, rbase, cbase, kb, tid);
  }

  int buf = 0, pbuf = 2;  // compute buffer index, prefetch buffer index (mod 3)
  for (int c = 0; c < NC; c++) {
    if (c == NC - 1) asm volatile("cp.async.wait_group 0;\n" ::: "memory");
    else             asm volatile("cp.async.wait_group 1;\n" ::: "memory");
    __syncthreads();  // chunk c landed; all warps done reading buf (from chunk c-1 epoch)

    if (c + 2 < NC) {  // prefetch c+2 BEFORE compute -> overlaps with HMMA below
      const __nv_bfloat16 *A, *B; int ld, kb;
      chunk_src<DISTILL>(c + 2, A, B, ld, kb);
      const uint32_t pb = sbase + (uint32_t)pbuf * BUF_BYTES;
      cp_chunk(pb, pb + 16384u, A, ld, B, ld, rbase, cbase, kb, tid);
    }

    const uint32_t sAb = sbase + (uint32_t)buf * BUF_BYTES;
    const uint32_t aRB = sAb + aRow;
    const uint32_t bRB = sAb + 16384u + bRow;
#pragma unroll
    for (int ks = 0; ks < 4; ks++) {
      const uint32_t acol = ((uint32_t)(ks * 32) + aSub) ^ aX;
      const uint32_t bcol = ((uint32_t)(ks * 32) + bSub) ^ bX;
      uint32_t af[4][4], bf0[4], bf1[4];
#pragma unroll
      for (int mt = 0; mt < 4; mt++) ldsm4(af[mt], aRB + mt * 2048u + acol);
      ldsm4(bf0, bRB + bcol);
      ldsm4(bf1, bRB + 2048u + bcol);
#pragma unroll
      for (int mt = 0; mt < 4; mt++) {
        mma16816(acc[mt][0], af[mt], &bf0[0]);
        mma16816(acc[mt][1], af[mt], &bf0[2]);
        mma16816(acc[mt][2], af[mt], &bf1[0]);
        mma16816(acc[mt][3], af[mt], &bf1[2]);
      }
    }
    buf = (buf + 1 == 3) ? 0 : buf + 1;
    pbuf = (pbuf + 1 == 3) ? 0 : pbuf + 1;
  }
}

// ---- fused pair kernel: distill triangle [0,528) + cont full grid [528,1552) ----
__global__ void __launch_bounds__(256, 2) pair_kernel(const uint8_t* __restrict__ mraw) {
  extern __shared__ char dsm[];
  char* dal = (char*)(((uintptr_t)dsm + 1023) & ~(uintptr_t)1023);
  const uint32_t sbase = smem_u32(dal);
  const int tid = threadIdx.x;

  float acc[4][4][4];
#pragma unroll
  for (int m = 0; m < 4; m++)
#pragma unroll
    for (int n = 0; n < 4; n++)
#pragma unroll
      for (int r = 0; r < 4; r++) acc[m][n][r] = 0.f;

  if (blockIdx.x < DIST_BLOCKS) {
    // ================= distillation (upper triangle, heavy: launch first) =================
    int p = blockIdx.x, ti = 0;
    while (p >= TILES - ti) { p -= TILES - ti; ti++; }
    const int tj = ti + p;
    const int rbase = ti * 128, cbase = tj * 128;
    const float wgt = (ti == tj) ? 1.f : 2.f;

    // acc := hash_sim/128 (K=128, pre-scaled), then -= teacher_sim (K=768, negated B)
    mma_mainloop<true>(acc, rbase, cbase, tid, sbase);

    float ss = 0.f;
#pragma unroll
    for (int m = 0; m < 4; m++)
#pragma unroll
      for (int n = 0; n < 4; n++)
#pragma unroll
        for (int r = 0; r < 4; r++) ss = fmaf(acc[m][n][r], acc[m][n][r], ss);
#pragma unroll
    for (int o = 16; o > 0; o >>= 1) ss += __shfl_down_sync(0xffffffffu, ss, o);
    __shared__ float red[8];
    if ((tid & 31) == 0) red[tid >> 5] = ss;
    __syncthreads();
    if (tid < 8) {
      float v = red[tid];
#pragma unroll
      for (int o = 4; o > 0; o >>= 1) v += __shfl_down_sync(0x000000ffu, v, o);
      if (tid == 0) atomicAdd(&g_distill, v * wgt);
    }
  } else {
    // ================= contrastive (full 32x32 grid, light: fills the tail) =============
    __shared__ float s_d[128], s_p[128], s_c[128];
    if (tid < 128) { s_d[tid] = 0.f; s_p[tid] = 0.f; s_c[tid] = 0.f; }
    const int bid2 = blockIdx.x - DIST_BLOCKS;
    const int ti = bid2 >> 5, tj = bid2 & 31;
    const int rbase = ti * 128, cbase = tj * 128;

    mma_mainloop<false>(acc, rbase, cbase, tid, sbase);

    // stage mask tile into smem (reuse buffer; dtype-robust probe)
    __syncthreads();
    uint8_t* mk = (uint8_t*)dal;
    const bool is_u8 = (mraw[4097] != 0);  // (1,1) diagonal true iff 1-byte layout
    if (is_u8) {
#pragma unroll
      for (int p = 0; p < 4; p++) {
        const int idx = tid + p * 256;
        const int row = idx >> 3, q = idx & 7;
        const uint4 v = *reinterpret_cast<const uint4*>(
            mraw + (size_t)(rbase + row) * NB + cbase + q * 16);
        *reinterpret_cast<uint4*>(&mk[row * 128 + q * 16]) = v;
      }
    } else {
      const uint32_t* m32 = reinterpret_cast<const uint32_t*>(mraw);
#pragma unroll
      for (int p = 0; p < 16; p++) {
        const int idx = tid + p * 256;
        const int row = idx >> 5, q = idx & 31;
        const uint4 v = *reinterpret_cast<const uint4*>(
            m32 + (size_t)(rbase + row) * NB + cbase + q * 4);
        uint8_t* d = &mk[row * 128 + q * 4];
        d[0] = (v.x != 0u); d[1] = (v.y != 0u); d[2] = (v.z != 0u); d[3] = (v.w != 0u);
      }
    }
    __syncthreads();

    const int lane = tid & 31, wid = tid >> 5;
    const int wm = (wid >> 2) * 64, wn = (wid & 3) * 32;
#pragma unroll
    for (int mt = 0; mt < 4; mt++) {
#pragma unroll
      for (int half = 0; half < 2; half++) {
        const int rl = wm + mt * 16 + (lane >> 2) + half * 8;
        const int gi = rbase + rl;
        float dsum = 0.f, psum = 0.f, csum = 0.f;
#pragma unroll
        for (int nt = 0; nt < 4; nt++) {
#pragma unroll
          for (int e = 0; e < 2; e++) {
            const int cl = wn + nt * 8 + (lane & 3) * 2 + e;
            const float s = acc[mt][nt][half * 2 + e] * INV_TEMP;
            if (gi != cbase + cl) dsum += __expf(s - INV_TEMP);
            if (mk[rl * 128 + cl]) { psum += s; csum += 1.f; }
          }
        }
        dsum += __shfl_down_sync(0xffffffffu, dsum, 2, 4);
        dsum += __shfl_down_sync(0xffffffffu, dsum, 1, 4);
        psum += __shfl_down_sync(0xffffffffu, psum, 2, 4);
        psum += __shfl_down_sync(0xffffffffu, psum, 1, 4);
        csum += __shfl_down_sync(0xffffffffu, csum, 2, 4);
        csum += __shfl_down_sync(0xffffffffu, csum, 1, 4);
        if ((lane & 3) == 0) {
          atomicAdd(&s_d[rl], dsum);
          atomicAdd(&s_p[rl], psum);
          atomicAdd(&s_c[rl], csum);
        }
      }
    }
    __syncthreads();
    if (tid < 128) {
      atomicAdd(&g_denom[rbase + tid], s_d[tid]);
      atomicAdd(&g_pos[rbase + tid], s_p[tid]);
      atomicAdd(&g_cnt[rbase + tid], s_c[tid]);
    }
  }
}

// ---------------- finalize ----------------
__global__ void finalize_kernel(float* __restrict__ out) {
  __shared__ double red[256];
  __shared__ float redq[256];
  double s = 0.0;
  for (int r = threadIdx.x; r < NB; r += 256) {
    const float c = fmaxf(g_cnt[r], 1.f);
    s += (double)(INV_TEMP + logf(g_denom[r]) - g_pos[r] / c);
  }
  float q = 0.f;
  for (int r = threadIdx.x; r < NB / 4; r += 256) q += g_qpart[r];
  red[threadIdx.x] = s;
  redq[threadIdx.x] = q;
  __syncthreads();
  for (int o = 128; o > 0; o >>= 1) {
    if (threadIdx.x < o) {
      red[threadIdx.x] += red[threadIdx.x + o];
      redq[threadIdx.x] += redq[threadIdx.x + o];
    }
    __syncthreads();
  }
  if (threadIdx.x == 0) {
    const double cont = red[0] / (double)NB;
    const double dist = (double)g_distill / ((double)NB * (double)NB);
    const double quant = (double)redq[0] / ((double)NB * (double)HB);
    out[0] = (float)(cont + 0.5 * dist + 0.01 * quant);
  }
}

// ---------------- launch ----------------
extern "C" void kernel_launch(void* const* d_in, const int* in_sizes, int n_in,
                              void* d_out, int out_size) {
  const float* logits = (const float*)d_in[0];
  const float* hash = (const float*)d_in[1];
  const float* teacher = (const float*)d_in[2];
  const uint8_t* mask = (const uint8_t*)d_in[3];
  float* out = (float*)d_out;
  (void)in_sizes; (void)n_in; (void)out_size;

  const int DSM = 3 * (int)BUF_BYTES + 1024;  // 3-stage pipeline + alignment slack
  cudaFuncSetAttribute(pair_kernel, cudaFuncAttributeMaxDynamicSharedMemorySize, DSM);

  prep_kernel<<<NB / 4, 128>>>(logits, hash, teacher);
  pair_kernel<<<DIST_BLOCKS + CONT_BLOCKS, 256, DSM>>>(mask);
  finalize_kernel<<<1, 256>>>(out);
}